// round 1
// baseline (speedup 1.0000x reference)
#include <cuda_runtime.h>
#include <math.h>

// ----------------------------------------------------------------------------
// Problem constants
// ----------------------------------------------------------------------------
#define BATCH   4
#define NPTS    4096
#define M_TOTAL (BATCH * NPTS)   // 16384
#define KNN     12
#define RD      320
#define NCLS    17

// ----------------------------------------------------------------------------
// Scratch (device global; allocation-free). Offsets in floats.
// ----------------------------------------------------------------------------
#define OFF_INFO   0ULL                      // [M,6]
#define OFF_ENCH   98304ULL                  // [M,96]
#define OFF_FP     1671168ULL                // [M,3,320]
#define OFF_GF     17399808ULL               // [M,320]
#define OFF_AIN    22642688ULL               // [M,480]
#define OFF_H1     30507008ULL               // [M,320]
#define OFF_FUSED  35749888ULL               // [M,320]
#define OFF_H2     40992768ULL               // [M,320]
#define SCRATCH_TOTAL 46235648ULL

__device__ __align__(256) float g_scratch[SCRATCH_TOTAL];

// ----------------------------------------------------------------------------
// Kernel 1: brute-force kNN + boundary features + confidence/entropy
// grid (NPTS/256, BATCH), block 256, dyn smem = 4096*16 + 4096*2 bytes
// ----------------------------------------------------------------------------
__global__ void knn_boundary_kernel(const float* __restrict__ pos,
                                    const int* __restrict__ labels,
                                    const float* __restrict__ logits,
                                    float* __restrict__ info)
{
    extern __shared__ float smemf[];
    float4* spos = (float4*)smemf;                              // 4096 * 16B
    unsigned short* slab = (unsigned short*)(spos + NPTS);      // 4096 * 2B

    const int b = blockIdx.y;
    const float* pb = pos + (size_t)b * NPTS * 3;
    const int* lb = labels + (size_t)b * NPTS;
    for (int j = threadIdx.x; j < NPTS; j += blockDim.x) {
        float x = pb[j * 3 + 0], y = pb[j * 3 + 1], z = pb[j * 3 + 2];
        spos[j] = make_float4(x, y, z, x * x + y * y + z * z);
        slab[j] = (unsigned short)lb[j];
    }
    __syncthreads();

    const int q = blockIdx.x * blockDim.x + threadIdx.x;
    const float4 pq = spos[q];
    const int mylab = slab[q];

    float bd[KNN];
    int   bj[KNN];
#pragma unroll
    for (int t = 0; t < KNN; t++) { bd[t] = 1e30f; bj[t] = 0; }

    for (int j = 0; j < NPTS; j++) {
        float4 pj = spos[j];
        float d2 = pq.w + pj.w - 2.0f * (pq.x * pj.x + pq.y * pj.y + pq.z * pj.z);
        if (j != q && d2 < bd[KNN - 1]) {
            bd[KNN - 1] = d2; bj[KNN - 1] = j;
#pragma unroll
            for (int s = KNN - 1; s > 0; s--) {
                if (bd[s] < bd[s - 1]) {
                    float td = bd[s]; bd[s] = bd[s - 1]; bd[s - 1] = td;
                    int   ti = bj[s]; bj[s] = bj[s - 1]; bj[s - 1] = ti;
                }
            }
        }
    }

    // Features from the 12 nearest neighbors (order-insensitive)
    float dist[KNN];
    float sumd = 0.f, ndiff = 0.f, sdsum = 0.f, nsame = 0.f, bmin = 1e30f;
#pragma unroll
    for (int t = 0; t < KNN; t++) {
        int j = bj[t];
        float4 pj = spos[j];
        float dx = pj.x - pq.x, dy = pj.y - pq.y, dz = pj.z - pq.z;
        float d = sqrtf(dx * dx + dy * dy + dz * dz);
        dist[t] = d;
        sumd += d;
        if (slab[j] != mylab) { ndiff += 1.f; bmin = fminf(bmin, d); }
        else                  { nsame += 1.f; sdsum += d; }
    }
    float mean_d = sumd / 12.0f;
    float var = 0.f;
#pragma unroll
    for (int t = 0; t < KNN; t++) { float dd = dist[t] - mean_d; var += dd * dd; }
    float stdd      = sqrtf(var / 11.0f);           // ddof=1
    float same_dist = sdsum / (nsame + 1e-6f);
    float bdist     = (ndiff > 0.f) ? bmin : same_dist;
    float bscore    = ndiff / 12.0f;
    float density   = 1.0f / (mean_d + 1e-6f);
    float curvature = stdd / (mean_d + 1e-6f);

    // softmax(logits / 0.75) -> confidence + normalized entropy
    const float* lg = logits + ((size_t)b * NPTS + q) * NCLS;
    float x[NCLS];
    float mx = -1e30f;
#pragma unroll
    for (int c = 0; c < NCLS; c++) { x[c] = lg[c] / 0.75f; mx = fmaxf(mx, x[c]); }
    float s = 0.f;
#pragma unroll
    for (int c = 0; c < NCLS; c++) { x[c] = expf(x[c] - mx); s += x[c]; }
    float invs = 1.0f / s;
    float conf = invs;  // max prob = exp(0)/s
    float ent = 0.f;
#pragma unroll
    for (int c = 0; c < NCLS; c++) {
        float p = x[c] * invs;
        ent -= p * logf(p + 1e-8f);
    }
    ent /= logf(17.0f);

    float* o = info + ((size_t)b * NPTS + q) * 6;
    o[0] = bscore; o[1] = conf; o[2] = ent; o[3] = density; o[4] = curvature; o[5] = bdist;
}

// ----------------------------------------------------------------------------
// Kernel 2: enc layer 1 (6 -> 96, relu). One thread per output element.
// ----------------------------------------------------------------------------
__global__ void enc1_kernel(const float* __restrict__ info,
                            const float* __restrict__ W,   // [6,96]
                            const float* __restrict__ b,   // [96]
                            float* __restrict__ out)       // [M,96]
{
    int idx = blockIdx.x * blockDim.x + threadIdx.x;
    if (idx >= M_TOTAL * 96) return;
    int m = idx / 96, o = idx % 96;
    const float* in = info + (size_t)m * 6;
    float s = b[o];
#pragma unroll
    for (int i = 0; i < 6; i++) s = fmaf(in[i], W[i * 96 + o], s);
    out[idx] = fmaxf(s, 0.f);
}

// ----------------------------------------------------------------------------
// Generic fp32 SIMT GEMM: C[M,N] = act(A[M,K] @ B[K,N] + bias) (+ resid)
// BM=64, BN=64, BK=16, 256 threads, 4x4 per thread.
// Requirements: M % 64 == 0, K % 16 == 0, N % 4 == 0, lda % 4 == 0, ldb == N.
// ----------------------------------------------------------------------------
__global__ void __launch_bounds__(256) gemm_f32(
    const float* __restrict__ A, int lda,
    const float* __restrict__ B, int ldb,
    const float* __restrict__ bias,
    const float* __restrict__ resid,   // may be null; row stride = ldc
    float* __restrict__ C, int ldc,
    int K, int N, int relu)
{
    __shared__ float As[16][65];   // [k][row], padded against bank conflicts
    __shared__ float Bs[16][64];   // [k][col]

    const int tid  = threadIdx.x;
    const int row0 = blockIdx.x * 64;
    const int col0 = blockIdx.y * 64;

    const int arow  = tid >> 2;          // 0..63
    const int akcol = (tid & 3) << 2;    // 0,4,8,12
    const int bkrow = tid >> 4;          // 0..15
    const int bcol  = (tid & 15) << 2;   // 0..60

    const int tx = tid & 15;
    const int ty = tid >> 4;

    float acc[4][4];
#pragma unroll
    for (int i = 0; i < 4; i++)
#pragma unroll
        for (int j = 0; j < 4; j++) acc[i][j] = 0.f;

    const float* Ap = A + (size_t)(row0 + arow) * lda + akcol;
    const float* Bp = B + (size_t)bkrow * ldb + col0 + bcol;
    const bool bin = (col0 + bcol) < N;   // N%4==0 so all-or-nothing per float4

    for (int k0 = 0; k0 < K; k0 += 16) {
        float4 av = *(const float4*)Ap;
        As[akcol + 0][arow] = av.x;
        As[akcol + 1][arow] = av.y;
        As[akcol + 2][arow] = av.z;
        As[akcol + 3][arow] = av.w;
        float4 bv = bin ? *(const float4*)Bp : make_float4(0.f, 0.f, 0.f, 0.f);
        *(float4*)&Bs[bkrow][bcol] = bv;
        __syncthreads();

#pragma unroll
        for (int kk = 0; kk < 16; kk++) {
            float a[4], bb[4];
#pragma unroll
            for (int i = 0; i < 4; i++) a[i] = As[kk][ty * 4 + i];
#pragma unroll
            for (int j = 0; j < 4; j++) bb[j] = Bs[kk][tx * 4 + j];
#pragma unroll
            for (int i = 0; i < 4; i++)
#pragma unroll
                for (int j = 0; j < 4; j++)
                    acc[i][j] = fmaf(a[i], bb[j], acc[i][j]);
        }
        __syncthreads();
        Ap += 16;
        Bp += (size_t)16 * ldb;
    }

#pragma unroll
    for (int i = 0; i < 4; i++) {
        int r = row0 + ty * 4 + i;
#pragma unroll
        for (int j = 0; j < 4; j++) {
            int c = col0 + tx * 4 + j;
            if (c < N) {
                float v = acc[i][j] + (bias ? bias[c] : 0.f);
                if (relu) v = fmaxf(v, 0.f);
                if (resid) v += resid[(size_t)r * ldc + c];
                C[(size_t)r * ldc + c] = v;
            }
        }
    }
}

// ----------------------------------------------------------------------------
// Kernel: global_feat = mean over 3 scales; also fills attn_in[:, :320].
// One thread per float4 chunk: M*80 threads.
// ----------------------------------------------------------------------------
__global__ void gf_kernel(const float* __restrict__ fp,   // [M,3,320]
                          float* __restrict__ gf,         // [M,320]
                          float* __restrict__ ain)        // [M,480]
{
    int idx = blockIdx.x * blockDim.x + threadIdx.x;
    int m = idx / 80;
    int c = (idx % 80) * 4;
    const float4 a = *(const float4*)(fp + (size_t)m * 960 + c);
    const float4 b = *(const float4*)(fp + (size_t)m * 960 + 320 + c);
    const float4 d = *(const float4*)(fp + (size_t)m * 960 + 640 + c);
    float4 g = make_float4((a.x + b.x + d.x) / 3.f, (a.y + b.y + d.y) / 3.f,
                           (a.z + b.z + d.z) / 3.f, (a.w + b.w + d.w) / 3.f);
    *(float4*)(gf  + (size_t)m * 320 + c) = g;
    *(float4*)(ain + (size_t)m * 480 + c) = g;
}

// ----------------------------------------------------------------------------
// Kernel: attn head (320 -> 3) + softmax. One warp per point.
// ----------------------------------------------------------------------------
__global__ void attn2_kernel(const float* __restrict__ h1,   // [M,320]
                             const float* __restrict__ Wa2,  // [320,3]
                             const float* __restrict__ ba2,  // [3]
                             float* __restrict__ attn_out)   // [M,3]
{
    int gtid = blockIdx.x * blockDim.x + threadIdx.x;
    int m = gtid >> 5;
    int lane = gtid & 31;
    if (m >= M_TOTAL) return;
    const float* h = h1 + (size_t)m * 320;
    float s0 = 0.f, s1 = 0.f, s2 = 0.f;
    for (int k = lane; k < 320; k += 32) {
        float hv = h[k];
        s0 = fmaf(hv, Wa2[k * 3 + 0], s0);
        s1 = fmaf(hv, Wa2[k * 3 + 1], s1);
        s2 = fmaf(hv, Wa2[k * 3 + 2], s2);
    }
#pragma unroll
    for (int off = 16; off > 0; off >>= 1) {
        s0 += __shfl_down_sync(0xffffffffu, s0, off);
        s1 += __shfl_down_sync(0xffffffffu, s1, off);
        s2 += __shfl_down_sync(0xffffffffu, s2, off);
    }
    if (lane == 0) {
        s0 += ba2[0]; s1 += ba2[1]; s2 += ba2[2];
        float mx = fmaxf(s0, fmaxf(s1, s2));
        float e0 = expf(s0 - mx), e1 = expf(s1 - mx), e2 = expf(s2 - mx);
        float inv = 1.f / (e0 + e1 + e2);
        attn_out[(size_t)m * 3 + 0] = e0 * inv;
        attn_out[(size_t)m * 3 + 1] = e1 * inv;
        attn_out[(size_t)m * 3 + 2] = e2 * inv;
    }
}

// ----------------------------------------------------------------------------
// Kernel: fused = sum_s attn_s * fp_s. One thread per float4 chunk.
// ----------------------------------------------------------------------------
__global__ void fused_kernel(const float* __restrict__ fp,     // [M,3,320]
                             const float* __restrict__ attn,   // [M,3]
                             float* __restrict__ fused)        // [M,320]
{
    int idx = blockIdx.x * blockDim.x + threadIdx.x;
    int m = idx / 80;
    int c = (idx % 80) * 4;
    float a0 = attn[(size_t)m * 3 + 0];
    float a1 = attn[(size_t)m * 3 + 1];
    float a2 = attn[(size_t)m * 3 + 2];
    const float4 x = *(const float4*)(fp + (size_t)m * 960 + c);
    const float4 y = *(const float4*)(fp + (size_t)m * 960 + 320 + c);
    const float4 z = *(const float4*)(fp + (size_t)m * 960 + 640 + c);
    float4 r;
    r.x = a0 * x.x + a1 * y.x + a2 * z.x;
    r.y = a0 * x.y + a1 * y.y + a2 * z.y;
    r.z = a0 * x.z + a1 * y.z + a2 * z.z;
    r.w = a0 * x.w + a1 * y.w + a2 * z.w;
    *(float4*)(fused + (size_t)m * 320 + c) = r;
}

// ----------------------------------------------------------------------------
// Host launcher
// ----------------------------------------------------------------------------
extern "C" void kernel_launch(void* const* d_in, const int* in_sizes, int n_in,
                              void* d_out, int out_size)
{
    const float* feat0  = (const float*)d_in[0];
    const float* feat1  = (const float*)d_in[1];
    const float* feat2  = (const float*)d_in[2];
    const float* logits = (const float*)d_in[3];
    const int*   labels = (const int*)  d_in[4];
    const float* pos    = (const float*)d_in[5];
    const float* Wp0  = (const float*)d_in[6];
    const float* bp0  = (const float*)d_in[7];
    const float* Wp1  = (const float*)d_in[8];
    const float* bp1  = (const float*)d_in[9];
    const float* Wp2  = (const float*)d_in[10];
    const float* bp2  = (const float*)d_in[11];
    const float* Wbe1 = (const float*)d_in[12];
    const float* bbe1 = (const float*)d_in[13];
    const float* Wbe2 = (const float*)d_in[14];
    const float* bbe2 = (const float*)d_in[15];
    const float* Wa1  = (const float*)d_in[16];
    const float* ba1  = (const float*)d_in[17];
    const float* Wa2  = (const float*)d_in[18];
    const float* ba2  = (const float*)d_in[19];
    const float* Wo1  = (const float*)d_in[20];
    const float* bo1  = (const float*)d_in[21];
    const float* Wo2  = (const float*)d_in[22];
    const float* bo2  = (const float*)d_in[23];

    float* S = nullptr;
    cudaGetSymbolAddress((void**)&S, g_scratch);

    float* info   = S + OFF_INFO;
    float* ench   = S + OFF_ENCH;
    float* fp     = S + OFF_FP;
    float* gf     = S + OFF_GF;
    float* ain    = S + OFF_AIN;
    float* h1     = S + OFF_H1;
    float* fusedb = S + OFF_FUSED;
    float* h2     = S + OFF_H2;

    float* out      = (float*)d_out;                       // [M,320]
    float* attn_out = out + (size_t)M_TOTAL * RD;          // [M,3]

    const int knn_smem = NPTS * 16 + NPTS * 2;             // 73728 B
    cudaFuncSetAttribute(knn_boundary_kernel,
                         cudaFuncAttributeMaxDynamicSharedMemorySize, knn_smem);

    // 1) kNN + boundary features
    knn_boundary_kernel<<<dim3(NPTS / 256, BATCH), 256, knn_smem>>>(
        pos, labels, logits, info);

    // 2) boundary encoder 6 -> 96 -> 160 (layer 2 writes attn_in[:, 320:480])
    enc1_kernel<<<(M_TOTAL * 96) / 256, 256>>>(info, Wbe1, bbe1, ench);
    gemm_f32<<<dim3(M_TOTAL / 64, 3), 256>>>(
        ench, 96, Wbe2, 160, bbe2, nullptr, ain + 320, 480, 96, 160, 1);

    // 3) feature projections -> fp[M,3,320]
    gemm_f32<<<dim3(M_TOTAL / 64, 5), 256>>>(
        feat0, 256, Wp0, 320, bp0, nullptr, fp + 0,   960, 256, 320, 0);
    gemm_f32<<<dim3(M_TOTAL / 64, 5), 256>>>(
        feat1, 512, Wp1, 320, bp1, nullptr, fp + 320, 960, 512, 320, 0);
    gemm_f32<<<dim3(M_TOTAL / 64, 5), 256>>>(
        feat2, 768, Wp2, 320, bp2, nullptr, fp + 640, 960, 768, 320, 0);

    // 4) global_feat = mean over scales; fills attn_in[:, :320]
    gf_kernel<<<(M_TOTAL * 80) / 256, 256>>>(fp, gf, ain);

    // 5) attention MLP: 480 -> 320 (relu), 320 -> 3 + softmax
    gemm_f32<<<dim3(M_TOTAL / 64, 5), 256>>>(
        ain, 480, Wa1, 320, ba1, nullptr, h1, 320, 480, 320, 1);
    attn2_kernel<<<(M_TOTAL * 32) / 256, 256>>>(h1, Wa2, ba2, attn_out);

    // 6) fused = sum_s attn_s * fp_s
    fused_kernel<<<(M_TOTAL * 80) / 256, 256>>>(fp, attn_out, fusedb);

    // 7) output MLP: 320 -> 320 (relu) -> 320, + global_feat residual
    gemm_f32<<<dim3(M_TOTAL / 64, 5), 256>>>(
        fusedb, 320, Wo1, 320, bo1, nullptr, h2, 320, 320, 320, 1);
    gemm_f32<<<dim3(M_TOTAL / 64, 5), 256>>>(
        h2, 320, Wo2, 320, bo2, gf, out, 320, 320, 320, 0);
}

// round 2
// speedup vs baseline: 1.2002x; 1.2002x over previous
#include <cuda_runtime.h>
#include <math.h>

// ----------------------------------------------------------------------------
// Problem constants
// ----------------------------------------------------------------------------
#define BATCH   4
#define NPTS    4096
#define M_TOTAL (BATCH * NPTS)   // 16384
#define KNN     12
#define RD      320
#define NCLS    17

// ----------------------------------------------------------------------------
// Scratch (device global; allocation-free). Offsets in floats.
// ----------------------------------------------------------------------------
#define OFF_INFO   0ULL                      // [M,6]
#define OFF_ENCH   98304ULL                  // [M,96]
#define OFF_FP     1671168ULL                // [M,3,320]
#define OFF_GF     17399808ULL               // [M,320]
#define OFF_AIN    22642688ULL               // [M,480]
#define OFF_H1     30507008ULL               // [M,320]
#define OFF_FUSED  35749888ULL               // [M,320]
#define OFF_H2     40992768ULL               // [M,320]
#define SCRATCH_TOTAL 46235648ULL

__device__ __align__(256) float g_scratch[SCRATCH_TOTAL];

// ----------------------------------------------------------------------------
// Kernel 1: brute-force kNN + boundary features + confidence/entropy
// grid (NPTS/64, BATCH), block 64, dyn smem = 4096*16 + 4096*2 bytes.
// Small blocks -> 256 blocks total so all 148 SMs get work.
// ----------------------------------------------------------------------------
__global__ void knn_boundary_kernel(const float* __restrict__ pos,
                                    const int* __restrict__ labels,
                                    const float* __restrict__ logits,
                                    float* __restrict__ info)
{
    extern __shared__ float smemf[];
    float4* spos = (float4*)smemf;                              // 4096 * 16B
    unsigned short* slab = (unsigned short*)(spos + NPTS);      // 4096 * 2B

    const int b = blockIdx.y;
    const float* pb = pos + (size_t)b * NPTS * 3;
    const int* lb = labels + (size_t)b * NPTS;
    for (int j = threadIdx.x; j < NPTS; j += blockDim.x) {
        float x = pb[j * 3 + 0], y = pb[j * 3 + 1], z = pb[j * 3 + 2];
        spos[j] = make_float4(x, y, z, x * x + y * y + z * z);
        slab[j] = (unsigned short)lb[j];
    }
    __syncthreads();

    const int q = blockIdx.x * blockDim.x + threadIdx.x;
    const float4 pq = spos[q];
    const int mylab = slab[q];

    float bd[KNN];
    int   bj[KNN];
#pragma unroll
    for (int t = 0; t < KNN; t++) { bd[t] = 1e30f; bj[t] = 0; }

#pragma unroll 4
    for (int j = 0; j < NPTS; j++) {
        float4 pj = spos[j];
        float d2 = pq.w + pj.w - 2.0f * (pq.x * pj.x + pq.y * pj.y + pq.z * pj.z);
        if (j != q && d2 < bd[KNN - 1]) {
            bd[KNN - 1] = d2; bj[KNN - 1] = j;
#pragma unroll
            for (int s = KNN - 1; s > 0; s--) {
                if (bd[s] < bd[s - 1]) {
                    float td = bd[s]; bd[s] = bd[s - 1]; bd[s - 1] = td;
                    int   ti = bj[s]; bj[s] = bj[s - 1]; bj[s - 1] = ti;
                }
            }
        }
    }

    // Features from the 12 nearest neighbors (order-insensitive)
    float dist[KNN];
    float sumd = 0.f, ndiff = 0.f, sdsum = 0.f, nsame = 0.f, bmin = 1e30f;
#pragma unroll
    for (int t = 0; t < KNN; t++) {
        int j = bj[t];
        float4 pj = spos[j];
        float dx = pj.x - pq.x, dy = pj.y - pq.y, dz = pj.z - pq.z;
        float d = sqrtf(dx * dx + dy * dy + dz * dz);
        dist[t] = d;
        sumd += d;
        if (slab[j] != mylab) { ndiff += 1.f; bmin = fminf(bmin, d); }
        else                  { nsame += 1.f; sdsum += d; }
    }
    float mean_d = sumd / 12.0f;
    float var = 0.f;
#pragma unroll
    for (int t = 0; t < KNN; t++) { float dd = dist[t] - mean_d; var += dd * dd; }
    float stdd      = sqrtf(var / 11.0f);           // ddof=1
    float same_dist = sdsum / (nsame + 1e-6f);
    float bdist     = (ndiff > 0.f) ? bmin : same_dist;
    float bscore    = ndiff / 12.0f;
    float density   = 1.0f / (mean_d + 1e-6f);
    float curvature = stdd / (mean_d + 1e-6f);

    // softmax(logits / 0.75) -> confidence + normalized entropy
    const float* lg = logits + ((size_t)b * NPTS + q) * NCLS;
    float x[NCLS];
    float mx = -1e30f;
#pragma unroll
    for (int c = 0; c < NCLS; c++) { x[c] = lg[c] / 0.75f; mx = fmaxf(mx, x[c]); }
    float s = 0.f;
#pragma unroll
    for (int c = 0; c < NCLS; c++) { x[c] = expf(x[c] - mx); s += x[c]; }
    float invs = 1.0f / s;
    float conf = invs;  // max prob = exp(0)/s
    float ent = 0.f;
#pragma unroll
    for (int c = 0; c < NCLS; c++) {
        float p = x[c] * invs;
        ent -= p * logf(p + 1e-8f);
    }
    ent /= logf(17.0f);

    float* o = info + ((size_t)b * NPTS + q) * 6;
    o[0] = bscore; o[1] = conf; o[2] = ent; o[3] = density; o[4] = curvature; o[5] = bdist;
}

// ----------------------------------------------------------------------------
// Kernel 2: enc layer 1 (6 -> 96, relu). One thread per output element.
// ----------------------------------------------------------------------------
__global__ void enc1_kernel(const float* __restrict__ info,
                            const float* __restrict__ W,   // [6,96]
                            const float* __restrict__ b,   // [96]
                            float* __restrict__ out)       // [M,96]
{
    int idx = blockIdx.x * blockDim.x + threadIdx.x;
    if (idx >= M_TOTAL * 96) return;
    int m = idx / 96, o = idx % 96;
    const float* in = info + (size_t)m * 6;
    float s = b[o];
#pragma unroll
    for (int i = 0; i < 6; i++) s = fmaf(in[i], W[i * 96 + o], s);
    out[idx] = fmaxf(s, 0.f);
}

// ----------------------------------------------------------------------------
// fp32 SIMT GEMM v2: C[M,N] = act(A[M,K] @ B[K,N] + bias) (+ resid)
// BM=128, BN=64, BK=16, 256 threads, 8x4 per thread, vectorized smem frags,
// register-staged global prefetch.
// Requirements: M % 128 == 0, K % 16 == 0, N % 4 == 0, lda % 4 == 0, ldb == N.
// ----------------------------------------------------------------------------
__global__ void __launch_bounds__(256) gemm_f32_v2(
    const float* __restrict__ A, int lda,
    const float* __restrict__ B, int ldb,
    const float* __restrict__ bias,
    const float* __restrict__ resid,   // may be null; row stride = ldc
    float* __restrict__ C, int ldc,
    int K, int N, int relu)
{
    __shared__ float As[16][132];   // [k][row], padded
    __shared__ float Bs[16][68];    // [k][col], padded

    const int tid  = threadIdx.x;
    const int row0 = blockIdx.x * 128;
    const int col0 = blockIdx.y * 64;

    // A load mapping: two float4 per thread (f = tid, tid+256)
    const int arow0 = tid >> 2;            // 0..63
    const int acg0  = (tid & 3) << 2;      // k-subcol: 0,4,8,12
    const int arow1 = arow0 + 64;
    // B load mapping: one float4 per thread
    const int bkrow = tid >> 4;            // 0..15
    const int bcol  = (tid & 15) << 2;     // 0..60

    // compute mapping
    const int tx = tid & 15;               // 16 cols of 4 -> 64
    const int ty = tid >> 4;               // 16 rows of 8 -> 128

    const float* Ap0 = A + (size_t)(row0 + arow0) * lda + acg0;
    const float* Ap1 = A + (size_t)(row0 + arow1) * lda + acg0;
    const float* Bp  = B + (size_t)bkrow * ldb + col0 + bcol;
    const bool bin = (col0 + bcol) < N;    // N % 4 == 0 -> all-or-nothing

    float acc[8][4];
#pragma unroll
    for (int i = 0; i < 8; i++)
#pragma unroll
        for (int j = 0; j < 4; j++) acc[i][j] = 0.f;

    // prefetch first tile into registers
    float4 ra0 = *(const float4*)Ap0;
    float4 ra1 = *(const float4*)Ap1;
    float4 rb  = bin ? *(const float4*)Bp : make_float4(0.f, 0.f, 0.f, 0.f);

    for (int k0 = 0; k0 < K; k0 += 16) {
        __syncthreads();   // previous compute done before overwriting smem
        As[acg0 + 0][arow0] = ra0.x;
        As[acg0 + 1][arow0] = ra0.y;
        As[acg0 + 2][arow0] = ra0.z;
        As[acg0 + 3][arow0] = ra0.w;
        As[acg0 + 0][arow1] = ra1.x;
        As[acg0 + 1][arow1] = ra1.y;
        As[acg0 + 2][arow1] = ra1.z;
        As[acg0 + 3][arow1] = ra1.w;
        *(float4*)&Bs[bkrow][bcol] = rb;
        __syncthreads();

        if (k0 + 16 < K) {
            Ap0 += 16; Ap1 += 16; Bp += (size_t)16 * ldb;
            ra0 = *(const float4*)Ap0;
            ra1 = *(const float4*)Ap1;
            rb  = bin ? *(const float4*)Bp : make_float4(0.f, 0.f, 0.f, 0.f);
        }

#pragma unroll
        for (int kk = 0; kk < 16; kk++) {
            float4 a0 = *(const float4*)&As[kk][ty * 8];
            float4 a1 = *(const float4*)&As[kk][ty * 8 + 4];
            float4 bf = *(const float4*)&Bs[kk][tx * 4];
            float a[8] = {a0.x, a0.y, a0.z, a0.w, a1.x, a1.y, a1.z, a1.w};
            float bb[4] = {bf.x, bf.y, bf.z, bf.w};
#pragma unroll
            for (int i = 0; i < 8; i++)
#pragma unroll
                for (int j = 0; j < 4; j++)
                    acc[i][j] = fmaf(a[i], bb[j], acc[i][j]);
        }
    }

    const int c = col0 + tx * 4;
    if (c < N) {
        float4 bv = bias ? *(const float4*)(bias + c) : make_float4(0.f, 0.f, 0.f, 0.f);
#pragma unroll
        for (int i = 0; i < 8; i++) {
            int r = row0 + ty * 8 + i;
            float4 v;
            v.x = acc[i][0] + bv.x;
            v.y = acc[i][1] + bv.y;
            v.z = acc[i][2] + bv.z;
            v.w = acc[i][3] + bv.w;
            if (relu) {
                v.x = fmaxf(v.x, 0.f); v.y = fmaxf(v.y, 0.f);
                v.z = fmaxf(v.z, 0.f); v.w = fmaxf(v.w, 0.f);
            }
            if (resid) {
                const float4 rv = *(const float4*)(resid + (size_t)r * ldc + c);
                v.x += rv.x; v.y += rv.y; v.z += rv.z; v.w += rv.w;
            }
            *(float4*)(C + (size_t)r * ldc + c) = v;
        }
    }
}

// ----------------------------------------------------------------------------
// Kernel: global_feat = mean over 3 scales; also fills attn_in[:, :320].
// ----------------------------------------------------------------------------
__global__ void gf_kernel(const float* __restrict__ fp,   // [M,3,320]
                          float* __restrict__ gf,         // [M,320]
                          float* __restrict__ ain)        // [M,480]
{
    int idx = blockIdx.x * blockDim.x + threadIdx.x;
    int m = idx / 80;
    int c = (idx % 80) * 4;
    const float4 a = *(const float4*)(fp + (size_t)m * 960 + c);
    const float4 b = *(const float4*)(fp + (size_t)m * 960 + 320 + c);
    const float4 d = *(const float4*)(fp + (size_t)m * 960 + 640 + c);
    float4 g = make_float4((a.x + b.x + d.x) / 3.f, (a.y + b.y + d.y) / 3.f,
                           (a.z + b.z + d.z) / 3.f, (a.w + b.w + d.w) / 3.f);
    *(float4*)(gf  + (size_t)m * 320 + c) = g;
    *(float4*)(ain + (size_t)m * 480 + c) = g;
}

// ----------------------------------------------------------------------------
// Kernel: attn head (320 -> 3) + softmax. One warp per point.
// ----------------------------------------------------------------------------
__global__ void attn2_kernel(const float* __restrict__ h1,   // [M,320]
                             const float* __restrict__ Wa2,  // [320,3]
                             const float* __restrict__ ba2,  // [3]
                             float* __restrict__ attn_out)   // [M,3]
{
    int gtid = blockIdx.x * blockDim.x + threadIdx.x;
    int m = gtid >> 5;
    int lane = gtid & 31;
    if (m >= M_TOTAL) return;
    const float* h = h1 + (size_t)m * 320;
    float s0 = 0.f, s1 = 0.f, s2 = 0.f;
    for (int k = lane; k < 320; k += 32) {
        float hv = h[k];
        s0 = fmaf(hv, Wa2[k * 3 + 0], s0);
        s1 = fmaf(hv, Wa2[k * 3 + 1], s1);
        s2 = fmaf(hv, Wa2[k * 3 + 2], s2);
    }
#pragma unroll
    for (int off = 16; off > 0; off >>= 1) {
        s0 += __shfl_down_sync(0xffffffffu, s0, off);
        s1 += __shfl_down_sync(0xffffffffu, s1, off);
        s2 += __shfl_down_sync(0xffffffffu, s2, off);
    }
    if (lane == 0) {
        s0 += ba2[0]; s1 += ba2[1]; s2 += ba2[2];
        float mx = fmaxf(s0, fmaxf(s1, s2));
        float e0 = expf(s0 - mx), e1 = expf(s1 - mx), e2 = expf(s2 - mx);
        float inv = 1.f / (e0 + e1 + e2);
        attn_out[(size_t)m * 3 + 0] = e0 * inv;
        attn_out[(size_t)m * 3 + 1] = e1 * inv;
        attn_out[(size_t)m * 3 + 2] = e2 * inv;
    }
}

// ----------------------------------------------------------------------------
// Kernel: fused = sum_s attn_s * fp_s. One thread per float4 chunk.
// ----------------------------------------------------------------------------
__global__ void fused_kernel(const float* __restrict__ fp,     // [M,3,320]
                             const float* __restrict__ attn,   // [M,3]
                             float* __restrict__ fused)        // [M,320]
{
    int idx = blockIdx.x * blockDim.x + threadIdx.x;
    int m = idx / 80;
    int c = (idx % 80) * 4;
    float a0 = attn[(size_t)m * 3 + 0];
    float a1 = attn[(size_t)m * 3 + 1];
    float a2 = attn[(size_t)m * 3 + 2];
    const float4 x = *(const float4*)(fp + (size_t)m * 960 + c);
    const float4 y = *(const float4*)(fp + (size_t)m * 960 + 320 + c);
    const float4 z = *(const float4*)(fp + (size_t)m * 960 + 640 + c);
    float4 r;
    r.x = a0 * x.x + a1 * y.x + a2 * z.x;
    r.y = a0 * x.y + a1 * y.y + a2 * z.y;
    r.z = a0 * x.z + a1 * y.z + a2 * z.z;
    r.w = a0 * x.w + a1 * y.w + a2 * z.w;
    *(float4*)(fused + (size_t)m * 320 + c) = r;
}

// ----------------------------------------------------------------------------
// Host launcher
// ----------------------------------------------------------------------------
extern "C" void kernel_launch(void* const* d_in, const int* in_sizes, int n_in,
                              void* d_out, int out_size)
{
    const float* feat0  = (const float*)d_in[0];
    const float* feat1  = (const float*)d_in[1];
    const float* feat2  = (const float*)d_in[2];
    const float* logits = (const float*)d_in[3];
    const int*   labels = (const int*)  d_in[4];
    const float* pos    = (const float*)d_in[5];
    const float* Wp0  = (const float*)d_in[6];
    const float* bp0  = (const float*)d_in[7];
    const float* Wp1  = (const float*)d_in[8];
    const float* bp1  = (const float*)d_in[9];
    const float* Wp2  = (const float*)d_in[10];
    const float* bp2  = (const float*)d_in[11];
    const float* Wbe1 = (const float*)d_in[12];
    const float* bbe1 = (const float*)d_in[13];
    const float* Wbe2 = (const float*)d_in[14];
    const float* bbe2 = (const float*)d_in[15];
    const float* Wa1  = (const float*)d_in[16];
    const float* ba1  = (const float*)d_in[17];
    const float* Wa2  = (const float*)d_in[18];
    const float* ba2  = (const float*)d_in[19];
    const float* Wo1  = (const float*)d_in[20];
    const float* bo1  = (const float*)d_in[21];
    const float* Wo2  = (const float*)d_in[22];
    const float* bo2  = (const float*)d_in[23];

    float* S = nullptr;
    cudaGetSymbolAddress((void**)&S, g_scratch);

    float* info   = S + OFF_INFO;
    float* ench   = S + OFF_ENCH;
    float* fp     = S + OFF_FP;
    float* gf     = S + OFF_GF;
    float* ain    = S + OFF_AIN;
    float* h1     = S + OFF_H1;
    float* fusedb = S + OFF_FUSED;
    float* h2     = S + OFF_H2;

    float* out      = (float*)d_out;                       // [M,320]
    float* attn_out = out + (size_t)M_TOTAL * RD;          // [M,3]

    const int knn_smem = NPTS * 16 + NPTS * 2;             // 73728 B
    cudaFuncSetAttribute(knn_boundary_kernel,
                         cudaFuncAttributeMaxDynamicSharedMemorySize, knn_smem);

    // 1) kNN + boundary features (256 blocks -> all SMs busy)
    knn_boundary_kernel<<<dim3(NPTS / 64, BATCH), 64, knn_smem>>>(
        pos, labels, logits, info);

    // 2) boundary encoder 6 -> 96 -> 160 (layer 2 writes attn_in[:, 320:480])
    enc1_kernel<<<(M_TOTAL * 96) / 256, 256>>>(info, Wbe1, bbe1, ench);
    gemm_f32_v2<<<dim3(M_TOTAL / 128, 3), 256>>>(
        ench, 96, Wbe2, 160, bbe2, nullptr, ain + 320, 480, 96, 160, 1);

    // 3) feature projections -> fp[M,3,320]
    gemm_f32_v2<<<dim3(M_TOTAL / 128, 5), 256>>>(
        feat0, 256, Wp0, 320, bp0, nullptr, fp + 0,   960, 256, 320, 0);
    gemm_f32_v2<<<dim3(M_TOTAL / 128, 5), 256>>>(
        feat1, 512, Wp1, 320, bp1, nullptr, fp + 320, 960, 512, 320, 0);
    gemm_f32_v2<<<dim3(M_TOTAL / 128, 5), 256>>>(
        feat2, 768, Wp2, 320, bp2, nullptr, fp + 640, 960, 768, 320, 0);

    // 4) global_feat = mean over scales; fills attn_in[:, :320]
    gf_kernel<<<(M_TOTAL * 80) / 256, 256>>>(fp, gf, ain);

    // 5) attention MLP: 480 -> 320 (relu), 320 -> 3 + softmax
    gemm_f32_v2<<<dim3(M_TOTAL / 128, 5), 256>>>(
        ain, 480, Wa1, 320, ba1, nullptr, h1, 320, 480, 320, 1);
    attn2_kernel<<<(M_TOTAL * 32) / 256, 256>>>(h1, Wa2, ba2, attn_out);

    // 6) fused = sum_s attn_s * fp_s
    fused_kernel<<<(M_TOTAL * 80) / 256, 256>>>(fp, attn_out, fusedb);

    // 7) output MLP: 320 -> 320 (relu) -> 320, + global_feat residual
    gemm_f32_v2<<<dim3(M_TOTAL / 128, 5), 256>>>(
        fusedb, 320, Wo1, 320, bo1, nullptr, h2, 320, 320, 320, 1);
    gemm_f32_v2<<<dim3(M_TOTAL / 128, 5), 256>>>(
        h2, 320, Wo2, 320, bo2, gf, out, 320, 320, 320, 0);
}

// round 3
// speedup vs baseline: 1.7657x; 1.4712x over previous
#include <cuda_runtime.h>
#include <math.h>

// ----------------------------------------------------------------------------
// Problem constants
// ----------------------------------------------------------------------------
#define BATCH   4
#define NPTS    4096
#define M_TOTAL (BATCH * NPTS)   // 16384
#define KNN     12
#define RD      320
#define NCLS    17

// ----------------------------------------------------------------------------
// Scratch (device global; allocation-free). Offsets in floats.
// ----------------------------------------------------------------------------
#define OFF_INFO   0ULL                      // [M,6]
#define OFF_ENCH   98304ULL                  // [M,96]
#define OFF_FP     1671168ULL                // [M,3,320]
#define OFF_GF     17399808ULL               // [M,320]
#define OFF_AIN    22642688ULL               // [M,480]
#define OFF_H1     30507008ULL               // [M,320]
#define OFF_FUSED  35749888ULL               // [M,320]
#define OFF_H2     40992768ULL               // [M,320]
#define SCRATCH_TOTAL 46235648ULL

__device__ __align__(256) float g_scratch[SCRATCH_TOTAL];

// ----------------------------------------------------------------------------
// Kernel 1: brute-force kNN + boundary features + confidence/entropy
// ----------------------------------------------------------------------------
__global__ void knn_boundary_kernel(const float* __restrict__ pos,
                                    const int* __restrict__ labels,
                                    const float* __restrict__ logits,
                                    float* __restrict__ info)
{
    extern __shared__ float smemf[];
    float4* spos = (float4*)smemf;                              // 4096 * 16B
    unsigned short* slab = (unsigned short*)(spos + NPTS);      // 4096 * 2B

    const int b = blockIdx.y;
    const float* pb = pos + (size_t)b * NPTS * 3;
    const int* lb = labels + (size_t)b * NPTS;
    for (int j = threadIdx.x; j < NPTS; j += blockDim.x) {
        float x = pb[j * 3 + 0], y = pb[j * 3 + 1], z = pb[j * 3 + 2];
        spos[j] = make_float4(x, y, z, x * x + y * y + z * z);
        slab[j] = (unsigned short)lb[j];
    }
    __syncthreads();

    const int q = blockIdx.x * blockDim.x + threadIdx.x;
    const float4 pq = spos[q];
    const int mylab = slab[q];

    float bd[KNN];
    int   bj[KNN];
#pragma unroll
    for (int t = 0; t < KNN; t++) { bd[t] = 1e30f; bj[t] = 0; }

#pragma unroll 4
    for (int j = 0; j < NPTS; j++) {
        float4 pj = spos[j];
        float d2 = pq.w + pj.w - 2.0f * (pq.x * pj.x + pq.y * pj.y + pq.z * pj.z);
        if (j != q && d2 < bd[KNN - 1]) {
            bd[KNN - 1] = d2; bj[KNN - 1] = j;
#pragma unroll
            for (int s = KNN - 1; s > 0; s--) {
                if (bd[s] < bd[s - 1]) {
                    float td = bd[s]; bd[s] = bd[s - 1]; bd[s - 1] = td;
                    int   ti = bj[s]; bj[s] = bj[s - 1]; bj[s - 1] = ti;
                }
            }
        }
    }

    float dist[KNN];
    float sumd = 0.f, ndiff = 0.f, sdsum = 0.f, nsame = 0.f, bmin = 1e30f;
#pragma unroll
    for (int t = 0; t < KNN; t++) {
        int j = bj[t];
        float4 pj = spos[j];
        float dx = pj.x - pq.x, dy = pj.y - pq.y, dz = pj.z - pq.z;
        float d = sqrtf(dx * dx + dy * dy + dz * dz);
        dist[t] = d;
        sumd += d;
        if (slab[j] != mylab) { ndiff += 1.f; bmin = fminf(bmin, d); }
        else                  { nsame += 1.f; sdsum += d; }
    }
    float mean_d = sumd / 12.0f;
    float var = 0.f;
#pragma unroll
    for (int t = 0; t < KNN; t++) { float dd = dist[t] - mean_d; var += dd * dd; }
    float stdd      = sqrtf(var / 11.0f);           // ddof=1
    float same_dist = sdsum / (nsame + 1e-6f);
    float bdist     = (ndiff > 0.f) ? bmin : same_dist;
    float bscore    = ndiff / 12.0f;
    float density   = 1.0f / (mean_d + 1e-6f);
    float curvature = stdd / (mean_d + 1e-6f);

    const float* lg = logits + ((size_t)b * NPTS + q) * NCLS;
    float x[NCLS];
    float mx = -1e30f;
#pragma unroll
    for (int c = 0; c < NCLS; c++) { x[c] = lg[c] / 0.75f; mx = fmaxf(mx, x[c]); }
    float s = 0.f;
#pragma unroll
    for (int c = 0; c < NCLS; c++) { x[c] = expf(x[c] - mx); s += x[c]; }
    float invs = 1.0f / s;
    float conf = invs;
    float ent = 0.f;
#pragma unroll
    for (int c = 0; c < NCLS; c++) {
        float p = x[c] * invs;
        ent -= p * logf(p + 1e-8f);
    }
    ent /= logf(17.0f);

    float* o = info + ((size_t)b * NPTS + q) * 6;
    o[0] = bscore; o[1] = conf; o[2] = ent; o[3] = density; o[4] = curvature; o[5] = bdist;
}

// ----------------------------------------------------------------------------
// Kernel 2: enc layer 1 (6 -> 96, relu)
// ----------------------------------------------------------------------------
__global__ void enc1_kernel(const float* __restrict__ info,
                            const float* __restrict__ W,   // [6,96]
                            const float* __restrict__ b,   // [96]
                            float* __restrict__ out)       // [M,96]
{
    int idx = blockIdx.x * blockDim.x + threadIdx.x;
    if (idx >= M_TOTAL * 96) return;
    int m = idx / 96, o = idx % 96;
    const float* in = info + (size_t)m * 6;
    float s = b[o];
#pragma unroll
    for (int i = 0; i < 6; i++) s = fmaf(in[i], W[i * 96 + o], s);
    out[idx] = fmaxf(s, 0.f);
}

// ----------------------------------------------------------------------------
// TF32 tensor-core GEMM: C[M,N] = act(A[M,K] @ B[K,N] + bias) (+ resid)
// BM=128, BN=64, BK=32, 256 threads (8 warps, 4x2), warp tile 32x32 via
// mma.sync.aligned.m16n8k8.row.col.f32.tf32.tf32.f32, fp32 accumulate.
// Requirements: M % 128 == 0, K % 32 == 0, N % 4 == 0, lda % 4 == 0, ldb == N.
// ----------------------------------------------------------------------------
__device__ __forceinline__ unsigned f2tf(float x) {
    unsigned u;
    asm("cvt.rna.tf32.f32 %0, %1;" : "=r"(u) : "f"(x));
    return u;
}

__device__ __forceinline__ void mma_tf32(float* d, const unsigned* a, const unsigned* b) {
    asm volatile(
        "mma.sync.aligned.m16n8k8.row.col.f32.tf32.tf32.f32 "
        "{%0,%1,%2,%3}, {%4,%5,%6,%7}, {%8,%9}, {%0,%1,%2,%3};"
        : "+f"(d[0]), "+f"(d[1]), "+f"(d[2]), "+f"(d[3])
        : "r"(a[0]), "r"(a[1]), "r"(a[2]), "r"(a[3]), "r"(b[0]), "r"(b[1]));
}

#define AP 133   // As row pad (conflict-free transposed stores)
#define BP 68    // Bs row pad

__global__ void __launch_bounds__(256) gemm_tf32(
    const float* __restrict__ A, int lda,
    const float* __restrict__ B, int ldb,
    const float* __restrict__ bias,
    const float* __restrict__ resid,   // may be null; row stride = ldc
    float* __restrict__ C, int ldc,
    int K, int N, int relu)
{
    __shared__ unsigned As[32][AP];   // [k][m]
    __shared__ unsigned Bs[32][BP];   // [k][n]

    const int tid  = threadIdx.x;
    const int lane = tid & 31;
    const int wid  = tid >> 5;
    const int row0 = blockIdx.x * 128;
    const int col0 = blockIdx.y * 64;

    const int wm = (wid & 3) * 32;    // warp row offset within tile
    const int wn = (wid >> 2) * 32;   // warp col offset within tile
    const int rq = lane >> 2;         // groupID 0..7
    const int kq = lane & 3;          // threadID_in_group 0..3

    // A staging: 4 float4/thread; idx = tid + 256*i; r = idx>>3, kc = (idx&7)*4
    // B staging: 2 float4/thread; idx = tid + 256*i; kr = idx>>4, nc = (idx&15)*4
    float4 pa[4], pb[2];
    const float* Aps[4];
    const float* Bps[2];
    int a_r[4], a_kc[4], b_kr[2], b_nc[2];
    bool b_in[2];
#pragma unroll
    for (int i = 0; i < 4; i++) {
        int idx = tid + 256 * i;
        a_r[i]  = idx >> 3;
        a_kc[i] = (idx & 7) << 2;
        Aps[i]  = A + (size_t)(row0 + a_r[i]) * lda + a_kc[i];
    }
#pragma unroll
    for (int i = 0; i < 2; i++) {
        int idx = tid + 256 * i;
        b_kr[i] = idx >> 4;
        b_nc[i] = (idx & 15) << 2;
        b_in[i] = (col0 + b_nc[i]) < N;   // N%4==0 -> all-or-nothing
        Bps[i]  = B + (size_t)b_kr[i] * ldb + col0 + b_nc[i];
    }

    float acc[2][4][4];
#pragma unroll
    for (int i = 0; i < 2; i++)
#pragma unroll
        for (int j = 0; j < 4; j++)
#pragma unroll
            for (int t = 0; t < 4; t++) acc[i][j][t] = 0.f;

    // prefetch first tile
#pragma unroll
    for (int i = 0; i < 4; i++) pa[i] = *(const float4*)Aps[i];
#pragma unroll
    for (int i = 0; i < 2; i++)
        pb[i] = b_in[i] ? *(const float4*)Bps[i] : make_float4(0.f, 0.f, 0.f, 0.f);

    for (int k0 = 0; k0 < K; k0 += 32) {
        __syncthreads();
#pragma unroll
        for (int i = 0; i < 4; i++) {
            As[a_kc[i] + 0][a_r[i]] = f2tf(pa[i].x);
            As[a_kc[i] + 1][a_r[i]] = f2tf(pa[i].y);
            As[a_kc[i] + 2][a_r[i]] = f2tf(pa[i].z);
            As[a_kc[i] + 3][a_r[i]] = f2tf(pa[i].w);
        }
#pragma unroll
        for (int i = 0; i < 2; i++) {
            Bs[b_kr[i]][b_nc[i] + 0] = f2tf(pb[i].x);
            Bs[b_kr[i]][b_nc[i] + 1] = f2tf(pb[i].y);
            Bs[b_kr[i]][b_nc[i] + 2] = f2tf(pb[i].z);
            Bs[b_kr[i]][b_nc[i] + 3] = f2tf(pb[i].w);
        }
        __syncthreads();

        if (k0 + 32 < K) {
#pragma unroll
            for (int i = 0; i < 4; i++) { Aps[i] += 32; pa[i] = *(const float4*)Aps[i]; }
#pragma unroll
            for (int i = 0; i < 2; i++) {
                Bps[i] += (size_t)32 * ldb;
                pb[i] = b_in[i] ? *(const float4*)Bps[i] : make_float4(0.f, 0.f, 0.f, 0.f);
            }
        }

#pragma unroll
        for (int ks = 0; ks < 4; ks++) {
            const int kb = ks * 8;
            unsigned a[2][4], b[4][2];
#pragma unroll
            for (int tm = 0; tm < 2; tm++) {
                const int r = wm + tm * 16 + rq;
                a[tm][0] = As[kb + kq]    [r];
                a[tm][1] = As[kb + kq]    [r + 8];
                a[tm][2] = As[kb + kq + 4][r];
                a[tm][3] = As[kb + kq + 4][r + 8];
            }
#pragma unroll
            for (int tn = 0; tn < 4; tn++) {
                const int c = wn + tn * 8 + rq;
                b[tn][0] = Bs[kb + kq]    [c];
                b[tn][1] = Bs[kb + kq + 4][c];
            }
#pragma unroll
            for (int tm = 0; tm < 2; tm++)
#pragma unroll
                for (int tn = 0; tn < 4; tn++)
                    mma_tf32(acc[tm][tn], a[tm], b[tn]);
        }
    }

    // Epilogue: c0/c1 at (row, col), c2/c3 at (row+8, col); col = 2*kq offset
#pragma unroll
    for (int tm = 0; tm < 2; tm++) {
        const int r = row0 + wm + tm * 16 + rq;
#pragma unroll
        for (int tn = 0; tn < 4; tn++) {
            const int c = col0 + wn + tn * 8 + kq * 2;
            if (c < N) {
                float b0 = bias ? bias[c] : 0.f;
                float b1 = bias ? bias[c + 1] : 0.f;
                float v0 = acc[tm][tn][0] + b0;
                float v1 = acc[tm][tn][1] + b1;
                float v2 = acc[tm][tn][2] + b0;
                float v3 = acc[tm][tn][3] + b1;
                if (relu) {
                    v0 = fmaxf(v0, 0.f); v1 = fmaxf(v1, 0.f);
                    v2 = fmaxf(v2, 0.f); v3 = fmaxf(v3, 0.f);
                }
                if (resid) {
                    const float2 r0 = *(const float2*)(resid + (size_t)r * ldc + c);
                    const float2 r1 = *(const float2*)(resid + (size_t)(r + 8) * ldc + c);
                    v0 += r0.x; v1 += r0.y; v2 += r1.x; v3 += r1.y;
                }
                *(float2*)(C + (size_t)r * ldc + c)       = make_float2(v0, v1);
                *(float2*)(C + (size_t)(r + 8) * ldc + c) = make_float2(v2, v3);
            }
        }
    }
}

// ----------------------------------------------------------------------------
// Kernel: global_feat = mean over 3 scales; also fills attn_in[:, :320].
// ----------------------------------------------------------------------------
__global__ void gf_kernel(const float* __restrict__ fp,   // [M,3,320]
                          float* __restrict__ gf,         // [M,320]
                          float* __restrict__ ain)        // [M,480]
{
    int idx = blockIdx.x * blockDim.x + threadIdx.x;
    int m = idx / 80;
    int c = (idx % 80) * 4;
    const float4 a = *(const float4*)(fp + (size_t)m * 960 + c);
    const float4 b = *(const float4*)(fp + (size_t)m * 960 + 320 + c);
    const float4 d = *(const float4*)(fp + (size_t)m * 960 + 640 + c);
    float4 g = make_float4((a.x + b.x + d.x) / 3.f, (a.y + b.y + d.y) / 3.f,
                           (a.z + b.z + d.z) / 3.f, (a.w + b.w + d.w) / 3.f);
    *(float4*)(gf  + (size_t)m * 320 + c) = g;
    *(float4*)(ain + (size_t)m * 480 + c) = g;
}

// ----------------------------------------------------------------------------
// Kernel: attn head (320 -> 3) + softmax. One warp per point.
// ----------------------------------------------------------------------------
__global__ void attn2_kernel(const float* __restrict__ h1,   // [M,320]
                             const float* __restrict__ Wa2,  // [320,3]
                             const float* __restrict__ ba2,  // [3]
                             float* __restrict__ attn_out)   // [M,3]
{
    int gtid = blockIdx.x * blockDim.x + threadIdx.x;
    int m = gtid >> 5;
    int lane = gtid & 31;
    if (m >= M_TOTAL) return;
    const float* h = h1 + (size_t)m * 320;
    float s0 = 0.f, s1 = 0.f, s2 = 0.f;
    for (int k = lane; k < 320; k += 32) {
        float hv = h[k];
        s0 = fmaf(hv, Wa2[k * 3 + 0], s0);
        s1 = fmaf(hv, Wa2[k * 3 + 1], s1);
        s2 = fmaf(hv, Wa2[k * 3 + 2], s2);
    }
#pragma unroll
    for (int off = 16; off > 0; off >>= 1) {
        s0 += __shfl_down_sync(0xffffffffu, s0, off);
        s1 += __shfl_down_sync(0xffffffffu, s1, off);
        s2 += __shfl_down_sync(0xffffffffu, s2, off);
    }
    if (lane == 0) {
        s0 += ba2[0]; s1 += ba2[1]; s2 += ba2[2];
        float mx = fmaxf(s0, fmaxf(s1, s2));
        float e0 = expf(s0 - mx), e1 = expf(s1 - mx), e2 = expf(s2 - mx);
        float inv = 1.f / (e0 + e1 + e2);
        attn_out[(size_t)m * 3 + 0] = e0 * inv;
        attn_out[(size_t)m * 3 + 1] = e1 * inv;
        attn_out[(size_t)m * 3 + 2] = e2 * inv;
    }
}

// ----------------------------------------------------------------------------
// Kernel: fused = sum_s attn_s * fp_s.
// ----------------------------------------------------------------------------
__global__ void fused_kernel(const float* __restrict__ fp,     // [M,3,320]
                             const float* __restrict__ attn,   // [M,3]
                             float* __restrict__ fused)        // [M,320]
{
    int idx = blockIdx.x * blockDim.x + threadIdx.x;
    int m = idx / 80;
    int c = (idx % 80) * 4;
    float a0 = attn[(size_t)m * 3 + 0];
    float a1 = attn[(size_t)m * 3 + 1];
    float a2 = attn[(size_t)m * 3 + 2];
    const float4 x = *(const float4*)(fp + (size_t)m * 960 + c);
    const float4 y = *(const float4*)(fp + (size_t)m * 960 + 320 + c);
    const float4 z = *(const float4*)(fp + (size_t)m * 960 + 640 + c);
    float4 r;
    r.x = a0 * x.x + a1 * y.x + a2 * z.x;
    r.y = a0 * x.y + a1 * y.y + a2 * z.y;
    r.z = a0 * x.z + a1 * y.z + a2 * z.z;
    r.w = a0 * x.w + a1 * y.w + a2 * z.w;
    *(float4*)(fused + (size_t)m * 320 + c) = r;
}

// ----------------------------------------------------------------------------
// Host launcher
// ----------------------------------------------------------------------------
extern "C" void kernel_launch(void* const* d_in, const int* in_sizes, int n_in,
                              void* d_out, int out_size)
{
    const float* feat0  = (const float*)d_in[0];
    const float* feat1  = (const float*)d_in[1];
    const float* feat2  = (const float*)d_in[2];
    const float* logits = (const float*)d_in[3];
    const int*   labels = (const int*)  d_in[4];
    const float* pos    = (const float*)d_in[5];
    const float* Wp0  = (const float*)d_in[6];
    const float* bp0  = (const float*)d_in[7];
    const float* Wp1  = (const float*)d_in[8];
    const float* bp1  = (const float*)d_in[9];
    const float* Wp2  = (const float*)d_in[10];
    const float* bp2  = (const float*)d_in[11];
    const float* Wbe1 = (const float*)d_in[12];
    const float* bbe1 = (const float*)d_in[13];
    const float* Wbe2 = (const float*)d_in[14];
    const float* bbe2 = (const float*)d_in[15];
    const float* Wa1  = (const float*)d_in[16];
    const float* ba1  = (const float*)d_in[17];
    const float* Wa2  = (const float*)d_in[18];
    const float* ba2  = (const float*)d_in[19];
    const float* Wo1  = (const float*)d_in[20];
    const float* bo1  = (const float*)d_in[21];
    const float* Wo2  = (const float*)d_in[22];
    const float* bo2  = (const float*)d_in[23];

    float* S = nullptr;
    cudaGetSymbolAddress((void**)&S, g_scratch);

    float* info   = S + OFF_INFO;
    float* ench   = S + OFF_ENCH;
    float* fp     = S + OFF_FP;
    float* gf     = S + OFF_GF;
    float* ain    = S + OFF_AIN;
    float* h1     = S + OFF_H1;
    float* fusedb = S + OFF_FUSED;
    float* h2     = S + OFF_H2;

    float* out      = (float*)d_out;                       // [M,320]
    float* attn_out = out + (size_t)M_TOTAL * RD;          // [M,3]

    const int knn_smem = NPTS * 16 + NPTS * 2;             // 73728 B
    cudaFuncSetAttribute(knn_boundary_kernel,
                         cudaFuncAttributeMaxDynamicSharedMemorySize, knn_smem);

    // 1) kNN + boundary features
    knn_boundary_kernel<<<dim3(NPTS / 64, BATCH), 64, knn_smem>>>(
        pos, labels, logits, info);

    // 2) boundary encoder 6 -> 96 -> 160 (layer 2 writes attn_in[:, 320:480])
    enc1_kernel<<<(M_TOTAL * 96) / 256, 256>>>(info, Wbe1, bbe1, ench);
    gemm_tf32<<<dim3(M_TOTAL / 128, 3), 256>>>(
        ench, 96, Wbe2, 160, bbe2, nullptr, ain + 320, 480, 96, 160, 1);

    // 3) feature projections -> fp[M,3,320]
    gemm_tf32<<<dim3(M_TOTAL / 128, 5), 256>>>(
        feat0, 256, Wp0, 320, bp0, nullptr, fp + 0,   960, 256, 320, 0);
    gemm_tf32<<<dim3(M_TOTAL / 128, 5), 256>>>(
        feat1, 512, Wp1, 320, bp1, nullptr, fp + 320, 960, 512, 320, 0);
    gemm_tf32<<<dim3(M_TOTAL / 128, 5), 256>>>(
        feat2, 768, Wp2, 320, bp2, nullptr, fp + 640, 960, 768, 320, 0);

    // 4) global_feat = mean over scales; fills attn_in[:, :320]
    gf_kernel<<<(M_TOTAL * 80) / 256, 256>>>(fp, gf, ain);

    // 5) attention MLP: 480 -> 320 (relu), 320 -> 3 + softmax
    gemm_tf32<<<dim3(M_TOTAL / 128, 5), 256>>>(
        ain, 480, Wa1, 320, ba1, nullptr, h1, 320, 480, 320, 1);
    attn2_kernel<<<(M_TOTAL * 32) / 256, 256>>>(h1, Wa2, ba2, attn_out);

    // 6) fused = sum_s attn_s * fp_s
    fused_kernel<<<(M_TOTAL * 80) / 256, 256>>>(fp, attn_out, fusedb);

    // 7) output MLP: 320 -> 320 (relu) -> 320, + global_feat residual
    gemm_tf32<<<dim3(M_TOTAL / 128, 5), 256>>>(
        fusedb, 320, Wo1, 320, bo1, nullptr, h2, 320, 320, 320, 1);
    gemm_tf32<<<dim3(M_TOTAL / 128, 5), 256>>>(
        h2, 320, Wo2, 320, bo2, gf, out, 320, 320, 320, 0);
}

// round 5
// speedup vs baseline: 1.8846x; 1.0673x over previous
#include <cuda_runtime.h>
#include <math.h>
#include <stdint.h>

// ----------------------------------------------------------------------------
// Problem constants
// ----------------------------------------------------------------------------
#define BATCH   4
#define NPTS    4096
#define M_TOTAL (BATCH * NPTS)   // 16384
#define KNN     12
#define RD      320
#define NCLS    17

// ----------------------------------------------------------------------------
// Scratch (device global; allocation-free). Offsets in floats.
// ----------------------------------------------------------------------------
#define OFF_INFO    0ULL           // [M,6]
#define OFF_ENCH96  98304ULL       // [M,96]
#define OFF_ENC160  1671168ULL     // [M,160]
#define OFF_FP      4292608ULL     // [M,3,320]
#define OFF_GF      20021248ULL    // [M,320]
#define OFF_H1      25264128ULL    // [M,320]
#define OFF_H2      30507008ULL    // [M,320]
#define SCRATCH_TOTAL 40992768ULL

__device__ __align__(256) float g_scratch[SCRATCH_TOTAL];

// tf32-rounded weight copies, [K,N] layout (same as inputs).
// be2 @0 (15360) | p0 @15360 (81920) | p1 @97280 (163840) | p2 @261120 (245760)
// a1 @506880 (153600) | o1 @660480 (102400) | o2 @762880 (102400)
#define WT_BE2 0
#define WT_P0  15360
#define WT_P1  97280
#define WT_P2  261120
#define WT_A1  506880
#define WT_O1  660480
#define WT_O2  762880
#define WT_TOTAL 865280
__device__ __align__(256) uint32_t g_wtf32[WT_TOTAL];

// ----------------------------------------------------------------------------
// Helpers
// ----------------------------------------------------------------------------
__device__ __forceinline__ uint32_t f2tf(float x) {
    uint32_t u;
    asm("cvt.rna.tf32.f32 %0, %1;" : "=r"(u) : "f"(x));
    return u;
}
__device__ __forceinline__ void mma_tf32(float* d, const uint32_t* a, const uint32_t* b) {
    asm volatile(
        "mma.sync.aligned.m16n8k8.row.col.f32.tf32.tf32.f32 "
        "{%0,%1,%2,%3}, {%4,%5,%6,%7}, {%8,%9}, {%0,%1,%2,%3};"
        : "+f"(d[0]), "+f"(d[1]), "+f"(d[2]), "+f"(d[3])
        : "r"(a[0]), "r"(a[1]), "r"(a[2]), "r"(a[3]), "r"(b[0]), "r"(b[1]));
}

// ----------------------------------------------------------------------------
// Kernel: round fp32 weights to tf32 (run once per weight, tiny)
// ----------------------------------------------------------------------------
__global__ void wcvt_kernel(const float* __restrict__ W, uint32_t* __restrict__ O, int n)
{
    int i = blockIdx.x * blockDim.x + threadIdx.x;
    if (i < n) O[i] = f2tf(W[i]);
}

// ----------------------------------------------------------------------------
// TF32 tensor-core GEMM v3.
// C[M,N] = act(A[M,K] @ B[K,N] + bias) (+ resid)
// BM=128, BN=64, BK=32, 128 threads (4 warps, 2x2), warp tile 64x32
// (tm=4 m16-tiles, tn=4 n8-tiles). Conflict-free smem:
//   As [m][k] pitch 36 (frag banks 4rq+kq, staging st.128 clean)
//   Bs [k][n] pitch 72 (frag banks 8kq+rq, staging st.128 clean)
// B is pre-rounded tf32 (g_wtf32) -> staging is a raw copy.
// MODE: 0 = A0 row-major lda
//       1 = concat: k<320 from A0 (ld 320), k>=320 from A1 (ld 160)
//       2 = fused:  A0 = fp [M,3,320], A1 = attn [M,3]; row = sum_s attn_s*fp_s
// Requirements: M%128==0, K%32==0, N%4==0.
// ----------------------------------------------------------------------------
template <int MODE>
__global__ void __launch_bounds__(128, 2) gemm_tf32_v3(
    const float* __restrict__ A0, const float* __restrict__ A1, int lda, int K,
    const uint32_t* __restrict__ B, int N,
    const float* __restrict__ bias, const float* __restrict__ resid,
    float* __restrict__ C, int ldc, int relu)
{
    __shared__ uint32_t As[128][36];
    __shared__ uint32_t Bs[32][72];

    const int tid  = threadIdx.x;
    const int lane = tid & 31;
    const int wid  = tid >> 5;
    const int row0 = blockIdx.x * 128;
    const int col0 = blockIdx.y * 64;

    const int wm = (wid >> 1) * 64;
    const int wn = (wid & 1) * 32;
    const int rq = lane >> 2;
    const int kq = lane & 3;

    // A staging: 1024 float4 / 128 thr = 8 each; idx = tid + i*128
    //   r = idx>>3 (0..127), kc = (idx&7)*4 (k-subcol)
    // B staging: 512 uint4 / 128 thr = 4 each; kr = idx>>4 (0..31), n4 = (idx&15)*4
    float4 pa[8];
    uint4  pb[4];

    float acc[4][4][4];
#pragma unroll
    for (int i = 0; i < 4; i++)
#pragma unroll
        for (int j = 0; j < 4; j++)
#pragma unroll
            for (int t = 0; t < 4; t++) acc[i][j][t] = 0.f;

    // ---- prefetch lambda-ish macros ----
#define LOAD_A(i, k0v)                                                          \
    {                                                                            \
        int idx = tid + (i) * 128;                                               \
        int r   = idx >> 3;                                                      \
        int k   = (k0v) + ((idx & 7) << 2);                                      \
        int rg  = row0 + r;                                                      \
        if (MODE == 0) {                                                         \
            pa[i] = *(const float4*)(A0 + (size_t)rg * lda + k);                 \
        } else if (MODE == 1) {                                                  \
            pa[i] = (k < 320)                                                    \
                ? *(const float4*)(A0 + (size_t)rg * 320 + k)                    \
                : *(const float4*)(A1 + (size_t)rg * 160 + (k - 320));           \
        } else {                                                                 \
            const float* f = A0 + (size_t)rg * 960 + k;                          \
            float4 x = *(const float4*)f;                                        \
            float4 y = *(const float4*)(f + 320);                                \
            float4 z = *(const float4*)(f + 640);                                \
            float w0 = A1[rg * 3 + 0], w1 = A1[rg * 3 + 1], w2 = A1[rg * 3 + 2]; \
            pa[i].x = w0 * x.x + w1 * y.x + w2 * z.x;                            \
            pa[i].y = w0 * x.y + w1 * y.y + w2 * z.y;                            \
            pa[i].z = w0 * x.z + w1 * y.z + w2 * z.z;                            \
            pa[i].w = w0 * x.w + w1 * y.w + w2 * z.w;                            \
        }                                                                        \
    }
#define LOAD_B(i, k0v)                                                          \
    {                                                                            \
        int idx = tid + (i) * 128;                                               \
        int kr  = idx >> 4;                                                      \
        int n4  = (idx & 15) << 2;                                               \
        pb[i] = ((col0 + n4) < N)                                                \
            ? *(const uint4*)(B + (size_t)((k0v) + kr) * N + col0 + n4)          \
            : make_uint4(0u, 0u, 0u, 0u);                                        \
    }

#pragma unroll
    for (int i = 0; i < 8; i++) LOAD_A(i, 0)
#pragma unroll
    for (int i = 0; i < 4; i++) LOAD_B(i, 0)

    for (int k0 = 0; k0 < K; k0 += 32) {
        __syncthreads();   // previous compute done before overwriting smem
#pragma unroll
        for (int i = 0; i < 8; i++) {
            int idx = tid + i * 128;
            int r   = idx >> 3;
            int kc  = (idx & 7) << 2;
            uint4 t;
            t.x = f2tf(pa[i].x); t.y = f2tf(pa[i].y);
            t.z = f2tf(pa[i].z); t.w = f2tf(pa[i].w);
            *(uint4*)&As[r][kc] = t;
        }
#pragma unroll
        for (int i = 0; i < 4; i++) {
            int idx = tid + i * 128;
            int kr  = idx >> 4;
            int n4  = (idx & 15) << 2;
            *(uint4*)&Bs[kr][n4] = pb[i];
        }
        __syncthreads();

        if (k0 + 32 < K) {
#pragma unroll
            for (int i = 0; i < 8; i++) LOAD_A(i, k0 + 32)
#pragma unroll
            for (int i = 0; i < 4; i++) LOAD_B(i, k0 + 32)
        }

#pragma unroll
        for (int ks = 0; ks < 4; ks++) {
            const int kb = ks * 8;
            uint32_t a[4][4], b[4][2];
#pragma unroll
            for (int tm = 0; tm < 4; tm++) {
                const int r = wm + tm * 16 + rq;
                a[tm][0] = As[r][kb + kq];
                a[tm][1] = As[r + 8][kb + kq];
                a[tm][2] = As[r][kb + kq + 4];
                a[tm][3] = As[r + 8][kb + kq + 4];
            }
#pragma unroll
            for (int tn = 0; tn < 4; tn++) {
                const int c = wn + tn * 8 + rq;
                b[tn][0] = Bs[kb + kq][c];
                b[tn][1] = Bs[kb + kq + 4][c];
            }
#pragma unroll
            for (int tm = 0; tm < 4; tm++)
#pragma unroll
                for (int tn = 0; tn < 4; tn++)
                    mma_tf32(acc[tm][tn], a[tm], b[tn]);
        }
    }
#undef LOAD_A
#undef LOAD_B

    // Epilogue: c0/c1 at (row, col..col+1), c2/c3 at (row+8, ...)
#pragma unroll
    for (int tm = 0; tm < 4; tm++) {
        const int r = row0 + wm + tm * 16 + rq;
#pragma unroll
        for (int tn = 0; tn < 4; tn++) {
            const int c = col0 + wn + tn * 8 + kq * 2;
            if (c < N) {
                float b0 = bias ? bias[c] : 0.f;
                float b1 = bias ? bias[c + 1] : 0.f;
                float v0 = acc[tm][tn][0] + b0;
                float v1 = acc[tm][tn][1] + b1;
                float v2 = acc[tm][tn][2] + b0;
                float v3 = acc[tm][tn][3] + b1;
                if (relu) {
                    v0 = fmaxf(v0, 0.f); v1 = fmaxf(v1, 0.f);
                    v2 = fmaxf(v2, 0.f); v3 = fmaxf(v3, 0.f);
                }
                if (resid) {
                    const float2 r0 = *(const float2*)(resid + (size_t)r * ldc + c);
                    const float2 r1 = *(const float2*)(resid + (size_t)(r + 8) * ldc + c);
                    v0 += r0.x; v1 += r0.y; v2 += r1.x; v3 += r1.y;
                }
                *(float2*)(C + (size_t)r * ldc + c)       = make_float2(v0, v1);
                *(float2*)(C + (size_t)(r + 8) * ldc + c) = make_float2(v2, v3);
            }
        }
    }
}

// ----------------------------------------------------------------------------
// Kernel: brute-force kNN + boundary features + confidence/entropy
// ----------------------------------------------------------------------------
__global__ void knn_boundary_kernel(const float* __restrict__ pos,
                                    const int* __restrict__ labels,
                                    const float* __restrict__ logits,
                                    float* __restrict__ info)
{
    extern __shared__ float smemf[];
    float4* spos = (float4*)smemf;
    unsigned short* slab = (unsigned short*)(spos + NPTS);

    const int b = blockIdx.y;
    const float* pb = pos + (size_t)b * NPTS * 3;
    const int* lb = labels + (size_t)b * NPTS;
    for (int j = threadIdx.x; j < NPTS; j += blockDim.x) {
        float x = pb[j * 3 + 0], y = pb[j * 3 + 1], z = pb[j * 3 + 2];
        spos[j] = make_float4(x, y, z, x * x + y * y + z * z);
        slab[j] = (unsigned short)lb[j];
    }
    __syncthreads();

    const int q = blockIdx.x * blockDim.x + threadIdx.x;
    const float4 pq = spos[q];
    const int mylab = slab[q];

    float bd[KNN];
    int   bj[KNN];
#pragma unroll
    for (int t = 0; t < KNN; t++) { bd[t] = 1e30f; bj[t] = 0; }

#pragma unroll 4
    for (int j = 0; j < NPTS; j++) {
        float4 pj = spos[j];
        float d2 = pq.w + pj.w - 2.0f * (pq.x * pj.x + pq.y * pj.y + pq.z * pj.z);
        if (j != q && d2 < bd[KNN - 1]) {
            bd[KNN - 1] = d2; bj[KNN - 1] = j;
#pragma unroll
            for (int s = KNN - 1; s > 0; s--) {
                if (bd[s] < bd[s - 1]) {
                    float td = bd[s]; bd[s] = bd[s - 1]; bd[s - 1] = td;
                    int   ti = bj[s]; bj[s] = bj[s - 1]; bj[s - 1] = ti;
                }
            }
        }
    }

    float dist[KNN];
    float sumd = 0.f, ndiff = 0.f, sdsum = 0.f, nsame = 0.f, bmin = 1e30f;
#pragma unroll
    for (int t = 0; t < KNN; t++) {
        int j = bj[t];
        float4 pj = spos[j];
        float dx = pj.x - pq.x, dy = pj.y - pq.y, dz = pj.z - pq.z;
        float d = sqrtf(dx * dx + dy * dy + dz * dz);
        dist[t] = d;
        sumd += d;
        if (slab[j] != mylab) { ndiff += 1.f; bmin = fminf(bmin, d); }
        else                  { nsame += 1.f; sdsum += d; }
    }
    float mean_d = sumd / 12.0f;
    float var = 0.f;
#pragma unroll
    for (int t = 0; t < KNN; t++) { float dd = dist[t] - mean_d; var += dd * dd; }
    float stdd      = sqrtf(var / 11.0f);
    float same_dist = sdsum / (nsame + 1e-6f);
    float bdist     = (ndiff > 0.f) ? bmin : same_dist;
    float bscore    = ndiff / 12.0f;
    float density   = 1.0f / (mean_d + 1e-6f);
    float curvature = stdd / (mean_d + 1e-6f);

    const float* lg = logits + ((size_t)b * NPTS + q) * NCLS;
    float x[NCLS];
    float mx = -1e30f;
#pragma unroll
    for (int c = 0; c < NCLS; c++) { x[c] = lg[c] / 0.75f; mx = fmaxf(mx, x[c]); }
    float s = 0.f;
#pragma unroll
    for (int c = 0; c < NCLS; c++) { x[c] = expf(x[c] - mx); s += x[c]; }
    float invs = 1.0f / s;
    float conf = invs;
    float ent = 0.f;
#pragma unroll
    for (int c = 0; c < NCLS; c++) {
        float p = x[c] * invs;
        ent -= p * logf(p + 1e-8f);
    }
    ent /= logf(17.0f);

    float* o = info + ((size_t)b * NPTS + q) * 6;
    o[0] = bscore; o[1] = conf; o[2] = ent; o[3] = density; o[4] = curvature; o[5] = bdist;
}

// ----------------------------------------------------------------------------
// Kernel: enc layer 1 (6 -> 96, relu)
// ----------------------------------------------------------------------------
__global__ void enc1_kernel(const float* __restrict__ info,
                            const float* __restrict__ W,
                            const float* __restrict__ b,
                            float* __restrict__ out)
{
    int idx = blockIdx.x * blockDim.x + threadIdx.x;
    if (idx >= M_TOTAL * 96) return;
    int m = idx / 96, o = idx % 96;
    const float* in = info + (size_t)m * 6;
    float s = b[o];
#pragma unroll
    for (int i = 0; i < 6; i++) s = fmaf(in[i], W[i * 96 + o], s);
    out[idx] = fmaxf(s, 0.f);
}

// ----------------------------------------------------------------------------
// Kernel: global_feat = mean over 3 scales.
// ----------------------------------------------------------------------------
__global__ void gf_kernel(const float* __restrict__ fp,
                          float* __restrict__ gf)
{
    int idx = blockIdx.x * blockDim.x + threadIdx.x;
    int m = idx / 80;
    int c = (idx % 80) * 4;
    const float4 a = *(const float4*)(fp + (size_t)m * 960 + c);
    const float4 b = *(const float4*)(fp + (size_t)m * 960 + 320 + c);
    const float4 d = *(const float4*)(fp + (size_t)m * 960 + 640 + c);
    float4 g = make_float4((a.x + b.x + d.x) / 3.f, (a.y + b.y + d.y) / 3.f,
                           (a.z + b.z + d.z) / 3.f, (a.w + b.w + d.w) / 3.f);
    *(float4*)(gf + (size_t)m * 320 + c) = g;
}

// ----------------------------------------------------------------------------
// Kernel: attn head (320 -> 3) + softmax. One warp per point.
// ----------------------------------------------------------------------------
__global__ void attn2_kernel(const float* __restrict__ h1,
                             const float* __restrict__ Wa2,
                             const float* __restrict__ ba2,
                             float* __restrict__ attn_out)
{
    int gtid = blockIdx.x * blockDim.x + threadIdx.x;
    int m = gtid >> 5;
    int lane = gtid & 31;
    if (m >= M_TOTAL) return;
    const float* h = h1 + (size_t)m * 320;
    float s0 = 0.f, s1 = 0.f, s2 = 0.f;
    for (int k = lane; k < 320; k += 32) {
        float hv = h[k];
        s0 = fmaf(hv, Wa2[k * 3 + 0], s0);
        s1 = fmaf(hv, Wa2[k * 3 + 1], s1);
        s2 = fmaf(hv, Wa2[k * 3 + 2], s2);
    }
#pragma unroll
    for (int off = 16; off > 0; off >>= 1) {
        s0 += __shfl_down_sync(0xffffffffu, s0, off);
        s1 += __shfl_down_sync(0xffffffffu, s1, off);
        s2 += __shfl_down_sync(0xffffffffu, s2, off);
    }
    if (lane == 0) {
        s0 += ba2[0]; s1 += ba2[1]; s2 += ba2[2];
        float mx = fmaxf(s0, fmaxf(s1, s2));
        float e0 = expf(s0 - mx), e1 = expf(s1 - mx), e2 = expf(s2 - mx);
        float inv = 1.f / (e0 + e1 + e2);
        attn_out[(size_t)m * 3 + 0] = e0 * inv;
        attn_out[(size_t)m * 3 + 1] = e1 * inv;
        attn_out[(size_t)m * 3 + 2] = e2 * inv;
    }
}

// ----------------------------------------------------------------------------
// Host launcher
// ----------------------------------------------------------------------------
extern "C" void kernel_launch(void* const* d_in, const int* in_sizes, int n_in,
                              void* d_out, int out_size)
{
    const float* feat0  = (const float*)d_in[0];
    const float* feat1  = (const float*)d_in[1];
    const float* feat2  = (const float*)d_in[2];
    const float* logits = (const float*)d_in[3];
    const int*   labels = (const int*)  d_in[4];
    const float* pos    = (const float*)d_in[5];
    const float* Wp0  = (const float*)d_in[6];
    const float* bp0  = (const float*)d_in[7];
    const float* Wp1  = (const float*)d_in[8];
    const float* bp1  = (const float*)d_in[9];
    const float* Wp2  = (const float*)d_in[10];
    const float* bp2  = (const float*)d_in[11];
    const float* Wbe1 = (const float*)d_in[12];
    const float* bbe1 = (const float*)d_in[13];
    const float* Wbe2 = (const float*)d_in[14];
    const float* bbe2 = (const float*)d_in[15];
    const float* Wa1  = (const float*)d_in[16];
    const float* ba1  = (const float*)d_in[17];
    const float* Wa2  = (const float*)d_in[18];
    const float* ba2  = (const float*)d_in[19];
    const float* Wo1  = (const float*)d_in[20];
    const float* bo1  = (const float*)d_in[21];
    const float* Wo2  = (const float*)d_in[22];
    const float* bo2  = (const float*)d_in[23];

    float* S = nullptr;
    cudaGetSymbolAddress((void**)&S, g_scratch);
    uint32_t* WT = nullptr;
    cudaGetSymbolAddress((void**)&WT, g_wtf32);

    float* info   = S + OFF_INFO;
    float* ench96 = S + OFF_ENCH96;
    float* enc160 = S + OFF_ENC160;
    float* fp     = S + OFF_FP;
    float* gf     = S + OFF_GF;
    float* h1     = S + OFF_H1;
    float* h2     = S + OFF_H2;

    float* out      = (float*)d_out;               // [M,320]
    float* attn_out = out + (size_t)M_TOTAL * RD;  // [M,3]

    const int knn_smem = NPTS * 16 + NPTS * 2;
    cudaFuncSetAttribute(knn_boundary_kernel,
                         cudaFuncAttributeMaxDynamicSharedMemorySize, knn_smem);

    // 0) round weights to tf32 once (deterministic; replayed every call)
    wcvt_kernel<<<(15360 + 255) / 256, 256>>>(Wbe2, WT + WT_BE2, 15360);
    wcvt_kernel<<<(81920 + 255) / 256, 256>>>(Wp0, WT + WT_P0, 81920);
    wcvt_kernel<<<(163840 + 255) / 256, 256>>>(Wp1, WT + WT_P1, 163840);
    wcvt_kernel<<<(245760 + 255) / 256, 256>>>(Wp2, WT + WT_P2, 245760);
    wcvt_kernel<<<(153600 + 255) / 256, 256>>>(Wa1, WT + WT_A1, 153600);
    wcvt_kernel<<<(102400 + 255) / 256, 256>>>(Wo1, WT + WT_O1, 102400);
    wcvt_kernel<<<(102400 + 255) / 256, 256>>>(Wo2, WT + WT_O2, 102400);

    // 1) kNN + boundary features
    knn_boundary_kernel<<<dim3(NPTS / 64, BATCH), 64, knn_smem>>>(
        pos, labels, logits, info);

    // 2) boundary encoder 6 -> 96 -> 160
    enc1_kernel<<<(M_TOTAL * 96) / 256, 256>>>(info, Wbe1, bbe1, ench96);
    gemm_tf32_v3<0><<<dim3(M_TOTAL / 128, 3), 128>>>(
        ench96, nullptr, 96, 96, WT + WT_BE2, 160, bbe2, nullptr, enc160, 160, 1);

    // 3) feature projections -> fp[M,3,320]
    gemm_tf32_v3<0><<<dim3(M_TOTAL / 128, 5), 128>>>(
        feat0, nullptr, 256, 256, WT + WT_P0, 320, bp0, nullptr, fp + 0, 960, 0);
    gemm_tf32_v3<0><<<dim3(M_TOTAL / 128, 5), 128>>>(
        feat1, nullptr, 512, 512, WT + WT_P1, 320, bp1, nullptr, fp + 320, 960, 0);
    gemm_tf32_v3<0><<<dim3(M_TOTAL / 128, 5), 128>>>(
        feat2, nullptr, 768, 768, WT + WT_P2, 320, bp2, nullptr, fp + 640, 960, 0);

    // 4) global_feat = mean over scales
    gf_kernel<<<(M_TOTAL * 80) / 256, 256>>>(fp, gf);

    // 5) attention MLP: [gf | enc160] (480) -> 320 relu, then 320 -> 3 softmax
    gemm_tf32_v3<1><<<dim3(M_TOTAL / 128, 5), 128>>>(
        gf, enc160, 0, 480, WT + WT_A1, 320, ba1, nullptr, h1, 320, 1);
    attn2_kernel<<<(M_TOTAL * 32) / 256, 256>>>(h1, Wa2, ba2, attn_out);

    // 6+7) fused projection folded into o1 staging; output MLP + residual
    gemm_tf32_v3<2><<<dim3(M_TOTAL / 128, 5), 128>>>(
        fp, attn_out, 0, 320, WT + WT_O1, 320, bo1, nullptr, h2, 320, 1);
    gemm_tf32_v3<0><<<dim3(M_TOTAL / 128, 5), 128>>>(
        h2, nullptr, 320, 320, WT + WT_O2, 320, bo2, gf, out, 320, 0);
}